// round 14
// baseline (speedup 1.0000x reference)
#include <cuda_runtime.h>

// ReprojectionLayer: project 40^3 grid thru 12 cameras, distort, clip,
// trilinear-upsample coords to 80^3, gather 23 joint heatmaps, mean over cams.
//
// R14 = merged prep (R9) + guarded ROW=25 gather (R5/R7, reverting R9's pad
// gather regression) + u16 pixel-index smem buffer replacing the 96 per-thread
// __shfl_sync in the gather address chain (6 STS + 48 LDS instead; -42 MIO
// ops/thread, shfl latency off the LDG chain).

#define NC 12
#define NJ 23
#define JP 32            // padded joints (128B line per pixel)
#define HS 130
#define HS2 (HS*HS)      // 16900
#define G  80
#define G2 40
#define G3 (G*G*G)

// Block tile of the 80^3 output
#define TI 8
#define TJ 4
#define TK 16
// Source patch per axis: T/2 + 2
#define SI 6
#define SJ 4
#define SK 10
#define NSRC (SI*SJ*SK)   // 240
#define NTHREADS 512

#define ROW 25           // staging row stride (coprime 32; q8<6 -> max idx 23)
#define PIXROW 9         // pixbuf row stride in u32 (9 coprime 32)

// smem (floats):
//   stage  [512][ROW]  = 12800 floats  [0, 12800)   (front aliases svq)
//   pixbuf [512][9] u32 = 4608 floats  [12800, 17408)
// svq (2880 ull = 5760 floats) lives in [0, 5760) until the barrier.
#define PIX_OFF 12800
#define SMEM_FLOATS (PIX_OFF + NTHREADS*PIXROW)
#define SMEM_BYTES  (SMEM_FLOATS * 4)       // 69632

typedef unsigned long long ull;

// 12*16900*32 floats = 25.9 MB scratch for transposed/padded heatmaps
__device__ float g_heatT[NC * HS2 * JP];
// projected+clipped coords per (cam, 40^3 grid point): 6.1 MB, L2-resident
__device__ float2 g_field[NC * G2 * G2 * G2];

// ---- packed f32x2 helpers ----
__device__ __forceinline__ ull mul2(ull a, ull b) {
    ull r; asm("mul.rn.f32x2 %0,%1,%2;" : "=l"(r) : "l"(a), "l"(b)); return r;
}
__device__ __forceinline__ ull fma2(ull a, ull b, ull c) {
    ull r; asm("fma.rn.f32x2 %0,%1,%2,%3;" : "=l"(r) : "l"(a), "l"(b), "l"(c)); return r;
}
__device__ __forceinline__ ull pack2(float x) {
    ull r; asm("mov.b64 %0,{%1,%1};" : "=l"(r) : "f"(x)); return r;
}

#define NTBLK (NC*HS)                    // 1560 transpose blocks
#define NPBLK ((NC*G2*G2*G2 + 255)/256)  // 3000 project blocks

// ---- Kernel 1: prep = transpose (C,J,HS,HS)->(C,HS,HS,32) + project field ----
__global__ __launch_bounds__(256)
void prep_kernel(const float* __restrict__ heat,
                 const float* __restrict__ center,
                 const float* __restrict__ cHM,
                 const float* __restrict__ Pm,
                 const float* __restrict__ Km,
                 const float* __restrict__ Dm) {
    if (blockIdx.x < NTBLK) {
        // ---- transpose part ----
        __shared__ float s[NJ][HS];
        const int c   = blockIdx.x / HS;
        const int row = blockIdx.x - c * HS;
        for (int t = threadIdx.x; t < NJ * HS; t += 256) {
            int j = t / HS, col = t - j * HS;
            s[j][col] = heat[((c * NJ + j) * HS + row) * HS + col];
        }
        __syncthreads();
        float* dst = g_heatT + (c * HS + row) * HS * JP;
        for (int t = threadIdx.x; t < HS * JP; t += 256) {
            int col = t >> 5, jj = t & 31;
            dst[t] = (jj < NJ) ? s[jj][col] : 0.0f;
        }
    } else {
        // ---- project part ----
        int t = (blockIdx.x - NTBLK) * 256 + threadIdx.x;
        if (t >= NC * G2 * G2 * G2) return;
        int c   = t / (G2*G2*G2);
        int r   = t - c * (G2*G2*G2);
        int i   = r / (G2*G2);
        int rem = r - i * (G2*G2);
        int j   = rem / G2;
        int k   = rem - j * G2;

        float X = (float)(i - 20) * 4.0f + center[0];
        float Y = (float)(j - 20) * 4.0f + center[1];
        float Z = (float)(k - 20) * 4.0f + center[2];
        const float* P = Pm + c*12;
        float p0 = X*P[0] + Y*P[3] + Z*P[6] + P[9];
        float p1 = X*P[1] + Y*P[4] + Z*P[7] + P[10];
        float p2 = X*P[2] + Y*P[5] + Z*P[8] + P[11];
        const float* Kc = Km + c*9;
        float fx = Kc[0], fy = Kc[4], cx = Kc[6], cy = Kc[7];
        float k1 = Dm[c*5+0], k2 = Dm[c*5+1];
        float v1 = p0/p2 - cx;
        float v2 = p1/p2 - cy;
        float ra = v1/fx, rb = v2/fy;
        float r2 = ra*ra + rb*rb;
        float dist = 1.0f + (k1 + k2*r2)*r2;
        v1 = v1*dist + cx;
        v2 = v2*dist + cy;
        float chx = cHM[c*2+0], chy = cHM[c*2+1];
        v1 = fminf(fmaxf(v1, chx - 129.0f), chx + 128.0f) - chx + 129.0f;
        v2 = fminf(fmaxf(v2, chy - 129.0f), chy + 128.0f) - chy + 129.0f;
        g_field[t] = make_float2(v1, v2);
    }
}

// per-axis upsample2x (align_corners=False) index+weight, relative to base0
__device__ __forceinline__ void axis_interp(int X, int base0,
                                            int& idx0, int& idx1, float& w) {
    if (X == 0)          { idx0 = 0 - base0;      idx1 = 1 - base0;      w = 0.f; }
    else if (X == G - 1) { idx0 = (G2-1) - base0; idx1 = idx0;           w = 0.f; }
    else { int i0 = (X - 1) >> 1; idx0 = i0 - base0; idx1 = idx0 + 1;
           w = (X & 1) ? 0.25f : 0.75f; }
}

// ---- Kernel 2: main ----
__global__ __launch_bounds__(NTHREADS, 3)
void reproj_kernel(float* __restrict__ out)           // (J,G,G,G)
{
    extern __shared__ float dyn[];
    ull*      svq   = reinterpret_cast<ull*>(dyn);       // [NC][NSRC]
    float*    stage = dyn;                               // [512][ROW], aliases svq
    unsigned* pixw  = reinterpret_cast<unsigned*>(dyn + PIX_OFF); // [512][PIXROW]

    const int tid = threadIdx.x;
    const int bI = blockIdx.z * TI;
    const int bJ = blockIdx.y * TJ;
    const int bK = blockIdx.x * TK;
    const int si0 = bI/2 - 1;
    const int sj0 = bJ/2 - 1;
    const int sk0 = bK/2 - 1;

    // ---- Phase 1: load the projected patch from the precomputed field ----
    const float2* fld = g_field;
    for (int t = tid; t < NC*NSRC; t += NTHREADS) {
        int c    = t / NSRC;
        int r    = t - c*NSRC;
        int i    = r / (SJ*SK);
        int rem  = r - i*(SJ*SK);
        int jj   = rem / SK;
        int kk   = rem - jj*SK;
        int gi = min(max(si0 + i,  0), G2-1);
        int gj = min(max(sj0 + jj, 0), G2-1);
        int gk = min(max(sk0 + kk, 0), G2-1);
        float2 v = __ldg(&fld[((c*G2 + gi)*G2 + gj)*G2 + gk]);
        svq[t] = (ull)__float_as_uint(v.x) | ((ull)__float_as_uint(v.y) << 32);
    }
    __syncthreads();

    // ---- Phase 2: packed trilinear lerp -> u16 pixel index per camera ----
    const int li = tid >> 6;           // 0..7
    const int lj = (tid >> 4) & 3;     // 0..3
    const int lk = tid & 15;           // 0..15
    const int I  = bI + li;
    const int Jo = bJ + lj;
    const int K  = bK + lk;

    int i0, i1, j0, j1, d0, d1;
    float wi, wj, wk;
    axis_interp(I,  si0, i0, i1, wi);
    axis_interp(Jo, sj0, j0, j1, wj);
    axis_interp(K,  sk0, d0, d1, wk);
    const ull WI = pack2(wi), OI = pack2(1.0f - wi);
    const ull WJ = pack2(wj), OJ = pack2(1.0f - wj);
    const ull WK = pack2(wk), OK = pack2(1.0f - wk);
    const int a0 = i0*(SJ*SK), a1 = i1*(SJ*SK);
    const int b0 = j0*SK,      b1 = j1*SK;

    unsigned pixpair[NC/2];
    #pragma unroll
    for (int c = 0; c < NC; c++) {
        const ull* s = svq + c*NSRC;
        ull t000 = s[a0+b0+d0], t100 = s[a1+b0+d0];
        ull t010 = s[a0+b1+d0], t110 = s[a1+b1+d0];
        ull t001 = s[a0+b0+d1], t101 = s[a1+b0+d1];
        ull t011 = s[a0+b1+d1], t111 = s[a1+b1+d1];
        ull u00 = fma2(t100, WI, mul2(t000, OI));
        ull u10 = fma2(t110, WI, mul2(t010, OI));
        ull u01 = fma2(t101, WI, mul2(t001, OI));
        ull u11 = fma2(t111, WI, mul2(t011, OI));
        ull w0  = fma2(u10, WJ, mul2(u00, OJ));
        ull w1  = fma2(u11, WJ, mul2(u01, OJ));
        ull V   = fma2(w1, WK, mul2(w0, OK));
        float V1 = __uint_as_float((unsigned)V);
        float V2 = __uint_as_float((unsigned)(V >> 32));
        int col = (int)(V1 * 0.5f);   // v >= 0, trunc == floor
        int row = (int)(V2 * 0.5f);
        unsigned p = (unsigned)(row*HS + col);  // <= 16768, fits u16
        if (c & 1) pixpair[c >> 1] |= (p << 16);
        else       pixpair[c >> 1] = p;
    }
    // store packed pixel indices (banks 9*tid+m: conflict-free per m)
    {
        unsigned* pp = pixw + tid * PIXROW;
        #pragma unroll
        for (int m = 0; m < NC/2; m++) pp[m] = pixpair[m];
    }
    __syncthreads();   // svq dead (stage may alias) + pixbuf visible

    const int lane = tid & 31;
    const int q8   = lane & 7;      // 16B piece within the 128B pixel line
    const int vsub = lane >> 3;     // voxel-in-4 within the gather quad
    float* wstage = stage + (tid & ~31) * ROW;
    float* tstage = stage + tid * ROW;
    const unsigned* wpix = pixw + (tid & ~31) * PIXROW;

    // ---- gather: quads of 4 voxels, one 128B line per voxel-cam ----
    const bool active = (q8 < 6);
    #pragma unroll
    for (int s8 = 0; s8 < 8; s8++) {
        const int dv = s8*4 + vsub;            // voxel slot [0,32) in warp
        // fetch this voxel's 12 packed pixel indices (broadcast LDS.32 x6)
        const unsigned* vp = wpix + dv * PIXROW;
        unsigned pr[NC/2];
        #pragma unroll
        for (int m = 0; m < NC/2; m++) pr[m] = vp[m];

        ull a0p = 0ull, a1p = 0ull;            // packed f32x2 accumulators
        #pragma unroll
        for (int c = 0; c < NC; c++) {
            unsigned p = (c & 1) ? (pr[c >> 1] >> 16) : (pr[c >> 1] & 0xffffu);
            if (active) {
                const ulonglong2* ptr = reinterpret_cast<const ulonglong2*>(
                    g_heatT + c*(HS2*JP) + (p << 5) + q8*4);
                ulonglong2 v = __ldg(ptr);
                asm("add.rn.f32x2 %0, %0, %1;" : "+l"(a0p) : "l"(v.x));
                asm("add.rn.f32x2 %0, %0, %1;" : "+l"(a1p) : "l"(v.y));
            }
        }
        if (active) {
            float* sp = wstage + dv*ROW + q8*4;   // banks 25dv+4q8: distinct
            sp[0] = __uint_as_float((unsigned)(a0p));
            sp[1] = __uint_as_float((unsigned)(a0p >> 32));
            sp[2] = __uint_as_float((unsigned)(a1p));
            sp[3] = __uint_as_float((unsigned)(a1p >> 32));
        }
    }
    __syncwarp();

    // ---- coalesced stores: thread owns its voxel, loops joints ----
    const int g = I*(G*G) + Jo*G + K;
    const float inv = 1.0f / 12.0f;
    float* op = out + g;
    #pragma unroll
    for (int j = 0; j < NJ; j++)
        op[j*G3] = tstage[j] * inv;
}

extern "C" void kernel_launch(void* const* d_in, const int* in_sizes, int n_in,
                              void* d_out, int out_size) {
    const float* heat   = (const float*)d_in[0];  // (1,C,J,HS,HS)
    const float* center = (const float*)d_in[1];  // (1,3)
    const float* cHM    = (const float*)d_in[2];  // (1,C,2)
    const float* Pm     = (const float*)d_in[3];  // (1,C,4,3)
    const float* Km     = (const float*)d_in[4];  // (1,C,3,3)
    const float* Dm     = (const float*)d_in[5];  // (1,C,1,5)
    float* out = (float*)d_out;                   // (1,J,80,80,80)

    cudaFuncSetAttribute(reproj_kernel,
                         cudaFuncAttributeMaxDynamicSharedMemorySize, SMEM_BYTES);

    prep_kernel<<<NTBLK + NPBLK, 256>>>(heat, center, cHM, Pm, Km, Dm);
    dim3 grid(G/TK, G/TJ, G/TI);  // (5,20,10)
    reproj_kernel<<<grid, NTHREADS, SMEM_BYTES>>>(out);
}

// round 15
// speedup vs baseline: 1.1992x; 1.1992x over previous
#include <cuda_runtime.h>

// ReprojectionLayer: project 40^3 grid thru 12 cameras, distort, clip,
// trilinear-upsample coords to 80^3, gather 23 joint heatmaps, mean over cams.
//
// R15 = best-of composition: R7's main kernel verbatim (guarded shfl gather,
// ROW=25, packed f32x2 lerp, precomputed field) + merged prep kernel (R13),
// with prep writing only the 24 read floats per 32-float pixel line.

#define NC 12
#define NJ 23
#define JP 32            // padded joints (128B line per pixel)
#define HS 130
#define HS2 (HS*HS)      // 16900
#define G  80
#define G2 40
#define G3 (G*G*G)

// Block tile of the 80^3 output
#define TI 8
#define TJ 4
#define TK 16
// Source patch per axis: T/2 + 2
#define SI 6
#define SJ 4
#define SK 10
#define NSRC (SI*SJ*SK)   // 240
#define NTHREADS 512

#define ROW 25           // staging row stride (coprime 32 -> conflict-free)

// smem: stage [512][ROW] floats = 51200B; svq (2880 ull = 23040B) aliases the
// front of stage (svq dead after pix computed; barrier before reuse).
#define SMEM_BYTES (NTHREADS * ROW * 4)

typedef unsigned long long ull;

// 12*16900*32 floats = 25.9 MB scratch for transposed/padded heatmaps
__device__ float g_heatT[NC * HS2 * JP];
// projected+clipped coords per (cam, 40^3 grid point): 6.1 MB, L2-resident
__device__ float2 g_field[NC * G2 * G2 * G2];

// ---- packed f32x2 helpers ----
__device__ __forceinline__ ull mul2(ull a, ull b) {
    ull r; asm("mul.rn.f32x2 %0,%1,%2;" : "=l"(r) : "l"(a), "l"(b)); return r;
}
__device__ __forceinline__ ull fma2(ull a, ull b, ull c) {
    ull r; asm("fma.rn.f32x2 %0,%1,%2,%3;" : "=l"(r) : "l"(a), "l"(b), "l"(c)); return r;
}
__device__ __forceinline__ ull pack2(float x) {
    ull r; asm("mov.b64 %0,{%1,%1};" : "=l"(r) : "f"(x)); return r;
}

#define NTBLK (NC*HS)                    // 1560 transpose blocks
#define NPBLK ((NC*G2*G2*G2 + 255)/256)  // 3000 project blocks

// ---- Kernel 1: prep = transpose (C,J,HS,HS)->(C,HS,HS,32) + project field ----
__global__ __launch_bounds__(256)
void prep_kernel(const float* __restrict__ heat,
                 const float* __restrict__ center,
                 const float* __restrict__ cHM,
                 const float* __restrict__ Pm,
                 const float* __restrict__ Km,
                 const float* __restrict__ Dm) {
    if (blockIdx.x < NTBLK) {
        // ---- transpose part ----
        __shared__ float s[NJ][HS];
        const int c   = blockIdx.x / HS;
        const int row = blockIdx.x - c * HS;
        for (int t = threadIdx.x; t < NJ * HS; t += 256) {
            int j = t / HS, col = t - j * HS;
            s[j][col] = heat[((c * NJ + j) * HS + row) * HS + col];
        }
        __syncthreads();
        // only floats 0..23 of each 32-float line are ever read (q8<6);
        // float 23 is the zero pad, floats 24..31 stay unwritten.
        float* dst = g_heatT + (c * HS + row) * HS * JP;
        for (int t = threadIdx.x; t < HS * JP; t += 256) {
            int col = t >> 5, jj = t & 31;
            if (jj < 24)
                dst[t] = (jj < NJ) ? s[jj][col] : 0.0f;
        }
    } else {
        // ---- project part ----
        int t = (blockIdx.x - NTBLK) * 256 + threadIdx.x;
        if (t >= NC * G2 * G2 * G2) return;
        int c   = t / (G2*G2*G2);
        int r   = t - c * (G2*G2*G2);
        int i   = r / (G2*G2);
        int rem = r - i * (G2*G2);
        int j   = rem / G2;
        int k   = rem - j * G2;

        float X = (float)(i - 20) * 4.0f + center[0];
        float Y = (float)(j - 20) * 4.0f + center[1];
        float Z = (float)(k - 20) * 4.0f + center[2];
        const float* P = Pm + c*12;
        float p0 = X*P[0] + Y*P[3] + Z*P[6] + P[9];
        float p1 = X*P[1] + Y*P[4] + Z*P[7] + P[10];
        float p2 = X*P[2] + Y*P[5] + Z*P[8] + P[11];
        const float* Kc = Km + c*9;
        float fx = Kc[0], fy = Kc[4], cx = Kc[6], cy = Kc[7];
        float k1 = Dm[c*5+0], k2 = Dm[c*5+1];
        float v1 = p0/p2 - cx;
        float v2 = p1/p2 - cy;
        float ra = v1/fx, rb = v2/fy;
        float r2 = ra*ra + rb*rb;
        float dist = 1.0f + (k1 + k2*r2)*r2;
        v1 = v1*dist + cx;
        v2 = v2*dist + cy;
        float chx = cHM[c*2+0], chy = cHM[c*2+1];
        v1 = fminf(fmaxf(v1, chx - 129.0f), chx + 128.0f) - chx + 129.0f;
        v2 = fminf(fmaxf(v2, chy - 129.0f), chy + 128.0f) - chy + 129.0f;
        g_field[t] = make_float2(v1, v2);
    }
}

// per-axis upsample2x (align_corners=False) index+weight, relative to base0
__device__ __forceinline__ void axis_interp(int X, int base0,
                                            int& idx0, int& idx1, float& w) {
    if (X == 0)          { idx0 = 0 - base0;      idx1 = 1 - base0;      w = 0.f; }
    else if (X == G - 1) { idx0 = (G2-1) - base0; idx1 = idx0;           w = 0.f; }
    else { int i0 = (X - 1) >> 1; idx0 = i0 - base0; idx1 = idx0 + 1;
           w = (X & 1) ? 0.25f : 0.75f; }
}

// ---- Kernel 2: main (R7 verbatim) ----
__global__ __launch_bounds__(NTHREADS, 3)
void reproj_kernel(float* __restrict__ out)           // (J,G,G,G)
{
    extern __shared__ float dyn[];
    ull*   svq   = reinterpret_cast<ull*>(dyn);  // [NC][NSRC] packed (v1,v2)
    float* stage = dyn;                          // [NTHREADS][ROW] (aliases sv)

    const int tid = threadIdx.x;
    const int bI = blockIdx.z * TI;
    const int bJ = blockIdx.y * TJ;
    const int bK = blockIdx.x * TK;
    const int si0 = bI/2 - 1;
    const int sj0 = bJ/2 - 1;
    const int sk0 = bK/2 - 1;

    // ---- Phase 1: load the projected patch from the precomputed field ----
    const float2* fld = g_field;
    for (int t = tid; t < NC*NSRC; t += NTHREADS) {
        int c    = t / NSRC;
        int r    = t - c*NSRC;
        int i    = r / (SJ*SK);
        int rem  = r - i*(SJ*SK);
        int jj   = rem / SK;
        int kk   = rem - jj*SK;
        int gi = min(max(si0 + i,  0), G2-1);
        int gj = min(max(sj0 + jj, 0), G2-1);
        int gk = min(max(sk0 + kk, 0), G2-1);
        float2 v = __ldg(&fld[((c*G2 + gi)*G2 + gj)*G2 + gk]);
        svq[t] = (ull)__float_as_uint(v.x) | ((ull)__float_as_uint(v.y) << 32);
    }
    __syncthreads();

    // ---- Phase 2: packed trilinear lerp -> pixel index per camera ----
    const int li = tid >> 6;           // 0..7
    const int lj = (tid >> 4) & 3;     // 0..3
    const int lk = tid & 15;           // 0..15
    const int I  = bI + li;
    const int Jo = bJ + lj;
    const int K  = bK + lk;

    int i0, i1, j0, j1, d0, d1;
    float wi, wj, wk;
    axis_interp(I,  si0, i0, i1, wi);
    axis_interp(Jo, sj0, j0, j1, wj);
    axis_interp(K,  sk0, d0, d1, wk);
    const ull WI = pack2(wi), OI = pack2(1.0f - wi);
    const ull WJ = pack2(wj), OJ = pack2(1.0f - wj);
    const ull WK = pack2(wk), OK = pack2(1.0f - wk);
    const int a0 = i0*(SJ*SK), a1 = i1*(SJ*SK);
    const int b0 = j0*SK,      b1 = j1*SK;

    int pix[NC];
    #pragma unroll
    for (int c = 0; c < NC; c++) {
        const ull* s = svq + c*NSRC;
        ull t000 = s[a0+b0+d0], t100 = s[a1+b0+d0];
        ull t010 = s[a0+b1+d0], t110 = s[a1+b1+d0];
        ull t001 = s[a0+b0+d1], t101 = s[a1+b0+d1];
        ull t011 = s[a0+b1+d1], t111 = s[a1+b1+d1];
        ull u00 = fma2(t100, WI, mul2(t000, OI));
        ull u10 = fma2(t110, WI, mul2(t010, OI));
        ull u01 = fma2(t101, WI, mul2(t001, OI));
        ull u11 = fma2(t111, WI, mul2(t011, OI));
        ull w0  = fma2(u10, WJ, mul2(u00, OJ));
        ull w1  = fma2(u11, WJ, mul2(u01, OJ));
        ull V   = fma2(w1, WK, mul2(w0, OK));
        float V1 = __uint_as_float((unsigned)V);
        float V2 = __uint_as_float((unsigned)(V >> 32));
        int col = (int)(V1 * 0.5f);   // v >= 0, trunc == floor
        int row = (int)(V2 * 0.5f);
        pix[c] = (c*HS2 + row*HS + col) << 5;   // word offset of 128B line
    }
    __syncthreads();   // svq dead; staging may alias it now

    const int lane = tid & 31;
    const int q8   = lane & 7;      // 16B piece within the 128B pixel line
    const int vsub = lane >> 3;     // voxel-in-4 within the gather quad
    float* wstage = stage + (tid & ~31) * ROW;
    float* tstage = stage + tid * ROW;

    // ---- gather: quads of 4 voxels; lanes q8<6 fetch the 23 real joints ----
    const bool active = (q8 < 6);
    #pragma unroll
    for (int s8 = 0; s8 < 8; s8++) {
        const int dv = s8*4 + vsub;            // voxel slot [0,32) in warp
        ull a0p = 0ull, a1p = 0ull;            // packed f32x2 accumulators
        #pragma unroll
        for (int c = 0; c < NC; c++) {
            int base = __shfl_sync(0xffffffffu, pix[c], dv);
            if (active) {
                const ulonglong2* ptr =
                    reinterpret_cast<const ulonglong2*>(g_heatT + base + q8*4);
                ulonglong2 v = __ldg(ptr);
                asm("add.rn.f32x2 %0, %0, %1;" : "+l"(a0p) : "l"(v.x));
                asm("add.rn.f32x2 %0, %0, %1;" : "+l"(a1p) : "l"(v.y));
            }
        }
        if (active) {
            float* sp = wstage + dv*ROW + q8*4;
            sp[0] = __uint_as_float((unsigned)(a0p));
            sp[1] = __uint_as_float((unsigned)(a0p >> 32));
            sp[2] = __uint_as_float((unsigned)(a1p));
            sp[3] = __uint_as_float((unsigned)(a1p >> 32));
        }
    }
    __syncwarp();

    // ---- coalesced stores: thread owns its voxel, loops joints ----
    const int g = I*(G*G) + Jo*G + K;
    const float inv = 1.0f / 12.0f;
    float* op = out + g;
    #pragma unroll
    for (int j = 0; j < NJ; j++)
        op[j*G3] = tstage[j] * inv;
}

extern "C" void kernel_launch(void* const* d_in, const int* in_sizes, int n_in,
                              void* d_out, int out_size) {
    const float* heat   = (const float*)d_in[0];  // (1,C,J,HS,HS)
    const float* center = (const float*)d_in[1];  // (1,3)
    const float* cHM    = (const float*)d_in[2];  // (1,C,2)
    const float* Pm     = (const float*)d_in[3];  // (1,C,4,3)
    const float* Km     = (const float*)d_in[4];  // (1,C,3,3)
    const float* Dm     = (const float*)d_in[5];  // (1,C,1,5)
    float* out = (float*)d_out;                   // (1,J,80,80,80)

    cudaFuncSetAttribute(reproj_kernel,
                         cudaFuncAttributeMaxDynamicSharedMemorySize, SMEM_BYTES);

    prep_kernel<<<NTBLK + NPBLK, 256>>>(heat, center, cHM, Pm, Km, Dm);
    dim3 grid(G/TK, G/TJ, G/TI);  // (5,20,10)
    reproj_kernel<<<grid, NTHREADS, SMEM_BYTES>>>(out);
}